// round 5
// baseline (speedup 1.0000x reference)
#include <cuda_runtime.h>
#include <cuda_bf16.h>
#include <cstdint>

// Packed-varlen (SEG=1024) causal attention + additive bias, fp32 I/O.
// Round 5: K/V pre-converted to bf16 hi/lo in a device scratch (one pre-pass
// kernel), main kernel cp.asyncs bf16 tiles directly (K double-buffered,
// V hidden behind QK+softmax). 3-product bf16 split on mma.sync.m16n8k16.

#define SQ   2048
#define NB   2
#define NHD  16
#define HD   128
#define SEG  1024
#define BM   128
#define BN   64
#define NT   512
#define ROWSTRIDE (NB*NHD*HD)
#define ATTN_SCALE 0.08838834764831845f

// scratch: per (b,h,s) one 512B row = [hi 128 bf16 | lo 128 bf16]
__device__ __align__(256) static unsigned char KHL[(size_t)NB * NHD * SQ * 512];
__device__ __align__(256) static unsigned char VHL[(size_t)NB * NHD * SQ * 512];

// smem layout (bytes); 272/144 row strides are ldmatrix conflict-free.
#define QSTRB 272
#define KSTRB 272
#define PSTRB 144
#define SM_QH 0                    // 128 x 272
#define SM_QL 34816
#define SM_KB 69632                // K double buffer: per buf [KH 64x272 | KL 64x272]
#define KBUF_SZ 34816
#define SM_VH 139264               // V single buffer
#define SM_VL 156672
#define SM_PH 174080               // 128 x 144
#define SM_PL 192512
#define SM_LB 210944               // l-buffer (2KB)
#define SMEM_TOTAL 212992

__device__ __forceinline__ uint32_t s2u(const void* p) {
    uint32_t a;
    asm("{ .reg .u64 t; cvta.to.shared.u64 t, %1; cvt.u32.u64 %0, t; }" : "=r"(a) : "l"(p));
    return a;
}
__device__ __forceinline__ void split2(float a, float b, uint32_t& hi, uint32_t& lo) {
    __nv_bfloat16 ah = __float2bfloat16_rn(a);
    __nv_bfloat16 bh = __float2bfloat16_rn(b);
    __nv_bfloat16 al = __float2bfloat16_rn(a - __bfloat162float(ah));
    __nv_bfloat16 bl = __float2bfloat16_rn(b - __bfloat162float(bh));
    hi = ((uint32_t)__bfloat16_as_ushort(bh) << 16) | __bfloat16_as_ushort(ah);
    lo = ((uint32_t)__bfloat16_as_ushort(bl) << 16) | __bfloat16_as_ushort(al);
}
__device__ __forceinline__ void ldsm4(uint32_t* r, uint32_t a) {
    asm volatile("ldmatrix.sync.aligned.m8n8.x4.shared.b16 {%0,%1,%2,%3}, [%4];"
                 : "=r"(r[0]), "=r"(r[1]), "=r"(r[2]), "=r"(r[3]) : "r"(a));
}
__device__ __forceinline__ void ldsm4t(uint32_t* r, uint32_t a) {
    asm volatile("ldmatrix.sync.aligned.m8n8.x4.trans.shared.b16 {%0,%1,%2,%3}, [%4];"
                 : "=r"(r[0]), "=r"(r[1]), "=r"(r[2]), "=r"(r[3]) : "r"(a));
}
__device__ __forceinline__ void mma16816(float* c, const uint32_t* a, const uint32_t* b) {
    asm volatile("mma.sync.aligned.m16n8k16.row.col.f32.bf16.bf16.f32 "
                 "{%0,%1,%2,%3}, {%4,%5,%6,%7}, {%8,%9}, {%0,%1,%2,%3};"
                 : "+f"(c[0]), "+f"(c[1]), "+f"(c[2]), "+f"(c[3])
                 : "r"(a[0]), "r"(a[1]), "r"(a[2]), "r"(a[3]), "r"(b[0]), "r"(b[1]));
}
#define CPASYNC16(s, g) asm volatile("cp.async.cg.shared.global [%0], [%1], 16;" :: "r"(s), "l"(g))
#define CPCOMMIT()      asm volatile("cp.async.commit_group;" ::: "memory")
#define CPWAIT0()       asm volatile("cp.async.wait_group 0;" ::: "memory")
#define CPWAIT1()       asm volatile("cp.async.wait_group 1;" ::: "memory")

// ---- pre-pass: K,V fp32 -> bf16 hi/lo rows in scratch ----
__global__ __launch_bounds__(256)
void convert_kv(const float* __restrict__ Kg, const float* __restrict__ Vg) {
    const int idx = blockIdx.x * 256 + threadIdx.x;     // 2,097,152 threads
    const int row = idx >> 5, f4 = idx & 31;
    const int bh = row >> 11, s = row & 2047;
    const size_t src = (size_t)s * ROWSTRIDE + bh * HD + f4 * 4;
    const size_t dst = (size_t)row * 512 + f4 * 8;
    float4 k = *(const float4*)(Kg + src);
    float4 v = *(const float4*)(Vg + src);
    uint32_t h0, l0, h1, l1;
    split2(k.x, k.y, h0, l0); split2(k.z, k.w, h1, l1);
    *(uint2*)(KHL + dst)       = make_uint2(h0, h1);
    *(uint2*)(KHL + dst + 256) = make_uint2(l0, l1);
    split2(v.x, v.y, h0, l0); split2(v.z, v.w, h1, l1);
    *(uint2*)(VHL + dst)       = make_uint2(h0, h1);
    *(uint2*)(VHL + dst + 256) = make_uint2(l0, l1);
}

__device__ __forceinline__ void issue_tile(const unsigned char* scratch, uint32_t sb,
                                           int smH, int smL, int bh, int g0, int tid) {
#pragma unroll
    for (int i = 0; i < 4; i++) {
        const int c = tid + NT * i, row = c >> 5, f4 = c & 31;
        const unsigned char* src = scratch + (((size_t)(bh * SQ + g0 + row)) << 9) + f4 * 16;
        const uint32_t dstb = (f4 < 16) ? (sb + smH + row * KSTRB + f4 * 16)
                                        : (sb + smL + row * KSTRB + (f4 - 16) * 16);
        CPASYNC16(dstb, src);
    }
}

__global__ __launch_bounds__(NT, 1)
void attn_hmma(const float* __restrict__ Qg, const float* __restrict__ Bias,
               float* __restrict__ Out) {
    extern __shared__ char smem[];
    const uint32_t sb = s2u(smem);
    const int tid = threadIdx.x, lane = tid & 31, warp = tid >> 5;
    const int mw = warp >> 2, nw = warp & 3;          // 4m x 4n warp grid
    const int m0 = mw * 32, tk0 = nw * 16, oc0 = nw * 32;
    const int tile = 15 - (int)blockIdx.x;
    const int head = blockIdx.y, batch = blockIdx.z;
    const int q0 = tile * BM, seg0 = (q0 / SEG) * SEG;
    const int bh = batch * NHD + head;
    const int base = bh * HD;
    const int nkt = (q0 - seg0) / BN + 2;

    // ---- prologue: prefetch K tile 0, then Q load + split ----
    issue_tile(KHL, sb, SM_KB, SM_KB + 17408, bh, seg0, tid);
    CPCOMMIT();
#pragma unroll
    for (int i = 0; i < 8; i++) {
        const int idx = tid + NT * i, row = idx >> 5, f4 = idx & 31;
        const float4 v = *(const float4*)(Qg + (size_t)(q0 + row) * ROWSTRIDE + base + f4 * 4);
        uint32_t h0, l0, h1, l1;
        split2(v.x, v.y, h0, l0); split2(v.z, v.w, h1, l1);
        *(uint2*)(smem + SM_QH + row * QSTRB + f4 * 8) = make_uint2(h0, h1);
        *(uint2*)(smem + SM_QL + row * QSTRB + f4 * 8) = make_uint2(l0, l1);
    }

    float o[2][4][4];
    float lsum[2][2] = {{0.f, 0.f}, {0.f, 0.f}};
#pragma unroll
    for (int mt = 0; mt < 2; mt++)
#pragma unroll
        for (int j = 0; j < 4; j++)
#pragma unroll
            for (int r = 0; r < 4; r++) o[mt][j][r] = 0.f;

    const int r0 = lane >> 2, cq = (lane & 3) * 2;

    for (int kt = 0; kt < nkt; kt++) {
        const int k0 = seg0 + kt * BN;
        const int kb = SM_KB + (kt & 1) * KBUF_SZ;
        CPWAIT0();            // K(kt) resident (V(kt-1) was waited last iter)
        __syncthreads();      // all warps done with prior-iter smem

        // V(kt) first, then K(kt+1): wait_group 1 below completes V.
        issue_tile(VHL, sb, SM_VH, SM_VL, bh, k0, tid);
        CPCOMMIT();
        const bool more = (kt + 1 < nkt);
        if (more) {
            issue_tile(KHL, sb, SM_KB + ((kt + 1) & 1) * KBUF_SZ,
                       SM_KB + ((kt + 1) & 1) * KBUF_SZ + 17408, bh, k0 + BN, tid);
            CPCOMMIT();
        }

        // ---- S = Q K^T (warp: 32 rows x 16 cols), 3-product bf16 split ----
        float c[2][2][4];
#pragma unroll
        for (int mt = 0; mt < 2; mt++)
#pragma unroll
            for (int j = 0; j < 2; j++)
#pragma unroll
                for (int r = 0; r < 4; r++) c[mt][j][r] = 0.f;

#pragma unroll
        for (int ks = 0; ks < 8; ks++) {
            uint32_t aH[2][4], aL[2][4], bH[4], bL[4];
#pragma unroll
            for (int mt = 0; mt < 2; mt++) {
                const uint32_t ad = sb + (m0 + 16 * mt + (lane & 15)) * QSTRB
                                  + ks * 32 + (lane >> 4) * 16;
                ldsm4(aH[mt], ad + SM_QH);
                ldsm4(aL[mt], ad + SM_QL);
            }
            const uint32_t bd = sb + kb + (tk0 + ((lane >> 4) & 1) * 8 + (lane & 7)) * KSTRB
                              + ks * 32 + ((lane >> 3) & 1) * 16;
            ldsm4(bH, bd);
            ldsm4(bL, bd + 17408);
#pragma unroll
            for (int mt = 0; mt < 2; mt++) {
                mma16816(c[mt][0], aH[mt], &bH[0]);
                mma16816(c[mt][0], aH[mt], &bL[0]);
                mma16816(c[mt][0], aL[mt], &bH[0]);
                mma16816(c[mt][1], aH[mt], &bH[2]);
                mma16816(c[mt][1], aH[mt], &bL[2]);
                mma16816(c[mt][1], aL[mt], &bH[2]);
            }
        }

        // ---- softmax (no max-sub) + bias + causal; P hi/lo -> smem ----
#pragma unroll
        for (int mt = 0; mt < 2; mt++) {
            const int qr0 = q0 + m0 + 16 * mt + r0;
            const int qr1 = qr0 + 8;
            const float* bp0 = Bias + (size_t)batch * SQ * SQ + (size_t)qr0 * SQ;
            const float* bp1 = Bias + (size_t)batch * SQ * SQ + (size_t)qr1 * SQ;
#pragma unroll
            for (int j = 0; j < 2; j++) {
                const int col = k0 + tk0 + j * 8 + cq;
                const float2 bb0 = __ldg((const float2*)(bp0 + col));
                const float2 bb1 = __ldg((const float2*)(bp1 + col));
                const float p00 = (col     <= qr0) ? __expf(c[mt][j][0] * ATTN_SCALE + bb0.x) : 0.f;
                const float p01 = (col + 1 <= qr0) ? __expf(c[mt][j][1] * ATTN_SCALE + bb0.y) : 0.f;
                const float p10 = (col     <= qr1) ? __expf(c[mt][j][2] * ATTN_SCALE + bb1.x) : 0.f;
                const float p11 = (col + 1 <= qr1) ? __expf(c[mt][j][3] * ATTN_SCALE + bb1.y) : 0.f;
                lsum[mt][0] += p00 + p01;
                lsum[mt][1] += p10 + p11;
                uint32_t h, l;
                const int off0 = (m0 + 16 * mt + r0) * PSTRB + (tk0 + j * 8 + cq) * 2;
                split2(p00, p01, h, l);
                *(uint32_t*)(smem + SM_PH + off0) = h;
                *(uint32_t*)(smem + SM_PL + off0) = l;
                split2(p10, p11, h, l);
                *(uint32_t*)(smem + SM_PH + off0 + 8 * PSTRB) = h;
                *(uint32_t*)(smem + SM_PL + off0 + 8 * PSTRB) = l;
            }
        }
        if (more) { CPWAIT1(); } else { CPWAIT0(); }   // V(kt) resident
        __syncthreads();                                // V + P visible to all

        // ---- O += P V (warp: 32 rows x 32 d-cols, K=64 tokens) ----
#pragma unroll
        for (int kk = 0; kk < 4; kk++) {
            uint32_t pH[2][4], pL[2][4];
#pragma unroll
            for (int mt = 0; mt < 2; mt++) {
                const uint32_t pd = sb + (m0 + 16 * mt + (lane & 15)) * PSTRB
                                  + kk * 32 + (lane >> 4) * 16;
                ldsm4(pH[mt], pd + SM_PH);
                ldsm4(pL[mt], pd + SM_PL);
            }
#pragma unroll
            for (int vp = 0; vp < 2; vp++) {
                const uint32_t vd = sb + (kk * 16 + ((lane >> 3) & 1) * 8 + (lane & 7)) * KSTRB
                                  + (oc0 + vp * 16 + (lane >> 4) * 8) * 2;
                uint32_t vH[4], vL[4];
                ldsm4t(vH, vd + SM_VH);
                ldsm4t(vL, vd + SM_VL);
#pragma unroll
                for (int mt = 0; mt < 2; mt++) {
                    mma16816(o[mt][2 * vp],     pH[mt], &vH[0]);
                    mma16816(o[mt][2 * vp],     pH[mt], &vL[0]);
                    mma16816(o[mt][2 * vp],     pL[mt], &vH[0]);
                    mma16816(o[mt][2 * vp + 1], pH[mt], &vH[2]);
                    mma16816(o[mt][2 * vp + 1], pH[mt], &vL[2]);
                    mma16816(o[mt][2 * vp + 1], pL[mt], &vH[2]);
                }
            }
        }
    }

    // ---- finalize: combine row sums across 4 n-warps, normalize, store ----
#pragma unroll
    for (int mt = 0; mt < 2; mt++)
#pragma unroll
        for (int r2 = 0; r2 < 2; r2++) {
            float v = lsum[mt][r2];
            v += __shfl_xor_sync(0xffffffffu, v, 1);
            v += __shfl_xor_sync(0xffffffffu, v, 2);
            lsum[mt][r2] = v;
        }
    if ((lane & 3) == 0) {
#pragma unroll
        for (int mt = 0; mt < 2; mt++)
#pragma unroll
            for (int r2 = 0; r2 < 2; r2++) {
                const int row = m0 + 16 * mt + r0 + 8 * r2;
                *(float*)(smem + SM_LB + (nw * 128 + row) * 4) = lsum[mt][r2];
            }
    }
    __syncthreads();

    float* outb = Out + ((size_t)bh * SQ) * HD;
#pragma unroll
    for (int mt = 0; mt < 2; mt++)
#pragma unroll
        for (int r2 = 0; r2 < 2; r2++) {
            const int row = m0 + 16 * mt + r0 + 8 * r2;
            const float lt = *(const float*)(smem + SM_LB + row * 4)
                           + *(const float*)(smem + SM_LB + (128 + row) * 4)
                           + *(const float*)(smem + SM_LB + (256 + row) * 4)
                           + *(const float*)(smem + SM_LB + (384 + row) * 4);
            const float inv = 1.0f / lt;
            float* op = outb + (size_t)(q0 + row) * HD + oc0 + cq;
#pragma unroll
            for (int j = 0; j < 4; j++) {
                float2 w;
                w.x = o[mt][j][r2 * 2 + 0] * inv;
                w.y = o[mt][j][r2 * 2 + 1] * inv;
                *(float2*)(op + j * 8) = w;
            }
        }
}

extern "C" void kernel_launch(void* const* d_in, const int* in_sizes, int n_in,
                              void* d_out, int out_size) {
    const float* Q    = (const float*)d_in[0];
    const float* K    = (const float*)d_in[1];
    const float* V    = (const float*)d_in[2];
    const float* Bias = (const float*)d_in[3];
    float* O = (float*)d_out;

    convert_kv<<<8192, 256>>>(K, V);   // 2*16*2048 rows x 32 f4

    cudaFuncSetAttribute(attn_hmma, cudaFuncAttributeMaxDynamicSharedMemorySize, SMEM_TOTAL);
    dim3 grid(SQ / BM, NHD, NB);       // (16,16,2) = 512 CTAs
    attn_hmma<<<grid, NT, SMEM_TOTAL>>>(Q, Bias, O);
}

// round 6
// speedup vs baseline: 1.1428x; 1.1428x over previous
#include <cuda_runtime.h>
#include <cuda_bf16.h>
#include <cstdint>

// Packed-varlen (SEG=1024) causal attention + additive bias, fp32 I/O.
// Round 6: 8 warps, each owns 16 q-rows x full k/d range. P stays in registers
// (S C-frags == PV A-frags), Q frags persistent in regs, K/V double-buffered
// cp.async from bf16 hi/lo scratch. One __syncthreads per k-tile.

#define SQ   2048
#define NB   2
#define NHD  16
#define HD   128
#define SEG  1024
#define BM   128
#define BN   64
#define NT   256
#define ROWSTRIDE (NB*NHD*HD)
#define ATTN_SCALE 0.08838834764831845f

// scratch: per (b,h,s) one 512B row = [hi 128 bf16 | lo 128 bf16]
__device__ __align__(256) static unsigned char KHL[(size_t)NB * NHD * SQ * 512];
__device__ __align__(256) static unsigned char VHL[(size_t)NB * NHD * SQ * 512];

// smem: K double buffer + V double buffer; Q staging aliases the V buffers.
// Each buffer: [H 64x272 | L 64x272] = 34816 B.
#define TSTR 272
#define TILE_H 17408
#define BUF_SZ 34816
#define SM_K 0                    // 2 x 34816
#define SM_V 69632                // 2 x 34816
#define SM_QSTG 69632             // prologue only: QH 128x272, QL at +34816
#define SMEM_TOTAL 139264

__device__ __forceinline__ uint32_t s2u(const void* p) {
    uint32_t a;
    asm("{ .reg .u64 t; cvta.to.shared.u64 t, %1; cvt.u32.u64 %0, t; }" : "=r"(a) : "l"(p));
    return a;
}
__device__ __forceinline__ void split2(float a, float b, uint32_t& hi, uint32_t& lo) {
    __nv_bfloat16 ah = __float2bfloat16_rn(a);
    __nv_bfloat16 bh = __float2bfloat16_rn(b);
    __nv_bfloat16 al = __float2bfloat16_rn(a - __bfloat162float(ah));
    __nv_bfloat16 bl = __float2bfloat16_rn(b - __bfloat162float(bh));
    hi = ((uint32_t)__bfloat16_as_ushort(bh) << 16) | __bfloat16_as_ushort(ah);
    lo = ((uint32_t)__bfloat16_as_ushort(bl) << 16) | __bfloat16_as_ushort(al);
}
__device__ __forceinline__ void ldsm4(uint32_t* r, uint32_t a) {
    asm volatile("ldmatrix.sync.aligned.m8n8.x4.shared.b16 {%0,%1,%2,%3}, [%4];"
                 : "=r"(r[0]), "=r"(r[1]), "=r"(r[2]), "=r"(r[3]) : "r"(a));
}
__device__ __forceinline__ void ldsm4t(uint32_t* r, uint32_t a) {
    asm volatile("ldmatrix.sync.aligned.m8n8.x4.trans.shared.b16 {%0,%1,%2,%3}, [%4];"
                 : "=r"(r[0]), "=r"(r[1]), "=r"(r[2]), "=r"(r[3]) : "r"(a));
}
__device__ __forceinline__ void mma16816(float* c, const uint32_t* a, const uint32_t* b) {
    asm volatile("mma.sync.aligned.m16n8k16.row.col.f32.bf16.bf16.f32 "
                 "{%0,%1,%2,%3}, {%4,%5,%6,%7}, {%8,%9}, {%0,%1,%2,%3};"
                 : "+f"(c[0]), "+f"(c[1]), "+f"(c[2]), "+f"(c[3])
                 : "r"(a[0]), "r"(a[1]), "r"(a[2]), "r"(a[3]), "r"(b[0]), "r"(b[1]));
}
#define CPASYNC16(s, g) asm volatile("cp.async.cg.shared.global [%0], [%1], 16;" :: "r"(s), "l"(g))
#define CPCOMMIT()      asm volatile("cp.async.commit_group;" ::: "memory")
#define CPWAIT0()       asm volatile("cp.async.wait_group 0;" ::: "memory")

// ---- pre-pass: K,V fp32 -> bf16 hi/lo rows in scratch ----
__global__ __launch_bounds__(256)
void convert_kv(const float* __restrict__ Kg, const float* __restrict__ Vg) {
    const int idx = blockIdx.x * 256 + threadIdx.x;
    const int row = idx >> 5, f4 = idx & 31;
    const int bh = row >> 11, s = row & 2047;
    const size_t src = (size_t)s * ROWSTRIDE + bh * HD + f4 * 4;
    const size_t dst = (size_t)row * 512 + f4 * 8;
    float4 k = *(const float4*)(Kg + src);
    float4 v = *(const float4*)(Vg + src);
    uint32_t h0, l0, h1, l1;
    split2(k.x, k.y, h0, l0); split2(k.z, k.w, h1, l1);
    *(uint2*)(KHL + dst)       = make_uint2(h0, h1);
    *(uint2*)(KHL + dst + 256) = make_uint2(l0, l1);
    split2(v.x, v.y, h0, l0); split2(v.z, v.w, h1, l1);
    *(uint2*)(VHL + dst)       = make_uint2(h0, h1);
    *(uint2*)(VHL + dst + 256) = make_uint2(l0, l1);
}

// cp.async one 64-row tile (hi+lo) from scratch into smem buffer at smbase.
__device__ __forceinline__ void issue_tile(const unsigned char* scratch, uint32_t sb,
                                           uint32_t smbase, int bh, int g0, int tid) {
#pragma unroll
    for (int i = 0; i < 8; i++) {
        const int c = tid + NT * i, row = c >> 5, f4 = c & 31;
        const unsigned char* src = scratch + (((size_t)(bh * SQ + g0 + row)) << 9) + f4 * 16;
        const uint32_t dst = (f4 < 16) ? (sb + smbase + row * TSTR + f4 * 16)
                                       : (sb + smbase + TILE_H + row * TSTR + (f4 - 16) * 16);
        CPASYNC16(dst, src);
    }
}

__global__ __launch_bounds__(NT, 1)
void attn_hmma(const float* __restrict__ Qg, const float* __restrict__ Bias,
               float* __restrict__ Out) {
    extern __shared__ char smem[];
    const uint32_t sb = s2u(smem);
    const int tid = threadIdx.x, lane = tid & 31, warp = tid >> 5;
    const int m0 = warp * 16;                 // warp's 16 q-rows
    const int tile = 15 - (int)blockIdx.x;
    const int head = blockIdx.y, batch = blockIdx.z;
    const int q0 = tile * BM, seg0 = (q0 / SEG) * SEG;
    const int bh = batch * NHD + head;
    const int base = bh * HD;
    const int nkt = (q0 - seg0) / BN + 2;

    // ---- prologue: K0 cp.async early; Q -> staging -> persistent frags ----
    issue_tile(KHL, sb, SM_K, bh, seg0, tid);
    CPCOMMIT();
#pragma unroll
    for (int i = 0; i < 16; i++) {
        const int idx = tid + NT * i, row = idx >> 5, f4 = idx & 31;
        const float4 v = *(const float4*)(Qg + (size_t)(q0 + row) * ROWSTRIDE + base + f4 * 4);
        uint32_t h0, l0, h1, l1;
        split2(v.x, v.y, h0, l0); split2(v.z, v.w, h1, l1);
        *(uint2*)(smem + SM_QSTG + row * TSTR + f4 * 8)         = make_uint2(h0, h1);
        *(uint2*)(smem + SM_QSTG + BUF_SZ + row * TSTR + f4 * 8) = make_uint2(l0, l1);
    }
    __syncthreads();
    uint32_t qH[8][4], qL[8][4];              // persistent Q fragments (64 regs)
#pragma unroll
    for (int ks = 0; ks < 8; ks++) {
        const uint32_t ad = sb + SM_QSTG + (m0 + (lane & 15)) * TSTR
                          + ks * 32 + (lane >> 4) * 16;
        ldsm4(qH[ks], ad);
        ldsm4(qL[ks], ad + BUF_SZ);
    }
    __syncthreads();                          // staging free -> V buffers
    issue_tile(VHL, sb, SM_V, bh, seg0, tid);
    CPCOMMIT();

    float o[16][4];
#pragma unroll
    for (int j = 0; j < 16; j++)
#pragma unroll
        for (int r = 0; r < 4; r++) o[j][r] = 0.f;
    float lsum0 = 0.f, lsum1 = 0.f;

    const int r0 = lane >> 2, q2 = (lane & 3) * 2;
    const int qr0 = q0 + m0 + r0, qr1 = qr0 + 8;
    const float* bp0 = Bias + (size_t)batch * SQ * SQ + (size_t)qr0 * SQ;
    const float* bp1 = Bias + (size_t)batch * SQ * SQ + (size_t)qr1 * SQ;

    for (int kt = 0; kt < nkt; kt++) {
        const int k0 = seg0 + kt * BN;
        const uint32_t kb = SM_K + (kt & 1) * BUF_SZ;
        const uint32_t vb = SM_V + (kt & 1) * BUF_SZ;
        CPWAIT0();           // K(kt), V(kt) resident
        __syncthreads();     // prior-iter readers of the other buffer done

        if (kt + 1 < nkt) {  // prefetch next tile into other buffer
            const uint32_t nb = (kt + 1) & 1;
            issue_tile(KHL, sb, SM_K + nb * BUF_SZ, bh, k0 + BN, tid);
            issue_tile(VHL, sb, SM_V + nb * BUF_SZ, bh, k0 + BN, tid);
            CPCOMMIT();
        }

        // ---- S = Q K^T : warp 16 rows x 64 cols, 3-product bf16 split ----
        float c[8][4];
#pragma unroll
        for (int f = 0; f < 8; f++)
#pragma unroll
            for (int r = 0; r < 4; r++) c[f][r] = 0.f;

#pragma unroll
        for (int ks = 0; ks < 8; ks++) {
            uint32_t bH[4][4], bL[4][4];
#pragma unroll
            for (int g = 0; g < 4; g++) {
                const uint32_t bd = sb + kb + (g * 16 + ((lane >> 4) & 1) * 8 + (lane & 7)) * TSTR
                                  + ks * 32 + ((lane >> 3) & 1) * 16;
                ldsm4(bH[g], bd);
                ldsm4(bL[g], bd + TILE_H);
            }
#pragma unroll
            for (int g = 0; g < 4; g++) {
                mma16816(c[2 * g],     qH[ks], &bH[g][0]);
                mma16816(c[2 * g],     qH[ks], &bL[g][0]);
                mma16816(c[2 * g],     qL[ks], &bH[g][0]);
                mma16816(c[2 * g + 1], qH[ks], &bH[g][2]);
                mma16816(c[2 * g + 1], qH[ks], &bL[g][2]);
                mma16816(c[2 * g + 1], qL[ks], &bH[g][2]);
            }
        }

        // ---- softmax (no max-sub; scores O(6)) + causal + bias, in regs ----
#pragma unroll
        for (int f = 0; f < 8; f++) {
            const int col = k0 + f * 8 + q2;
            const float2 b0 = __ldg((const float2*)(bp0 + col));
            const float2 b1 = __ldg((const float2*)(bp1 + col));
            const float p0 = (col     <= qr0) ? __expf(c[f][0] * ATTN_SCALE + b0.x) : 0.f;
            const float p1 = (col + 1 <= qr0) ? __expf(c[f][1] * ATTN_SCALE + b0.y) : 0.f;
            const float p2 = (col     <= qr1) ? __expf(c[f][2] * ATTN_SCALE + b1.x) : 0.f;
            const float p3 = (col + 1 <= qr1) ? __expf(c[f][3] * ATTN_SCALE + b1.y) : 0.f;
            lsum0 += p0 + p1;
            lsum1 += p2 + p3;
            c[f][0] = p0; c[f][1] = p1; c[f][2] = p2; c[f][3] = p3;
        }
        // pack S C-frags into PV A-frags (hi/lo) — no smem round trip
        uint32_t pH[4][4], pL[4][4];
#pragma unroll
        for (int t = 0; t < 4; t++) {
            split2(c[2 * t][0],     c[2 * t][1],     pH[t][0], pL[t][0]);
            split2(c[2 * t][2],     c[2 * t][3],     pH[t][1], pL[t][1]);
            split2(c[2 * t + 1][0], c[2 * t + 1][1], pH[t][2], pL[t][2]);
            split2(c[2 * t + 1][2], c[2 * t + 1][3], pH[t][3], pL[t][3]);
        }

        // ---- O += P V : warp 16 rows x 128 d-cols over 64 tokens ----
#pragma unroll
        for (int kk = 0; kk < 4; kk++) {
#pragma unroll
            for (int vp = 0; vp < 8; vp++) {
                const uint32_t vd = sb + vb + (kk * 16 + ((lane >> 3) & 1) * 8 + (lane & 7)) * TSTR
                                  + (vp * 16 + (lane >> 4) * 8) * 2;
                uint32_t vH[4], vL[4];
                ldsm4t(vH, vd);
                ldsm4t(vL, vd + TILE_H);
                mma16816(o[2 * vp],     pH[kk], &vH[0]);
                mma16816(o[2 * vp],     pH[kk], &vL[0]);
                mma16816(o[2 * vp],     pL[kk], &vH[0]);
                mma16816(o[2 * vp + 1], pH[kk], &vH[2]);
                mma16816(o[2 * vp + 1], pH[kk], &vL[2]);
                mma16816(o[2 * vp + 1], pL[kk], &vH[2]);
            }
        }
    }

    // ---- finalize: row sums are warp-local (xor over the 4-lane quad) ----
    lsum0 += __shfl_xor_sync(0xffffffffu, lsum0, 1);
    lsum0 += __shfl_xor_sync(0xffffffffu, lsum0, 2);
    lsum1 += __shfl_xor_sync(0xffffffffu, lsum1, 1);
    lsum1 += __shfl_xor_sync(0xffffffffu, lsum1, 2);
    const float inv0 = 1.0f / lsum0, inv1 = 1.0f / lsum1;

    float* op0 = Out + ((size_t)bh * SQ + qr0) * HD + q2;
    float* op1 = Out + ((size_t)bh * SQ + qr1) * HD + q2;
#pragma unroll
    for (int vp = 0; vp < 8; vp++) {
#pragma unroll
        for (int h = 0; h < 2; h++) {
            const int col = vp * 16 + h * 8;
            float2 w0, w1;
            w0.x = o[2 * vp + h][0] * inv0; w0.y = o[2 * vp + h][1] * inv0;
            w1.x = o[2 * vp + h][2] * inv1; w1.y = o[2 * vp + h][3] * inv1;
            *(float2*)(op0 + col) = w0;
            *(float2*)(op1 + col) = w1;
        }
    }
}

extern "C" void kernel_launch(void* const* d_in, const int* in_sizes, int n_in,
                              void* d_out, int out_size) {
    const float* Q    = (const float*)d_in[0];
    const float* K    = (const float*)d_in[1];
    const float* V    = (const float*)d_in[2];
    const float* Bias = (const float*)d_in[3];
    float* O = (float*)d_out;

    convert_kv<<<8192, 256>>>(K, V);

    cudaFuncSetAttribute(attn_hmma, cudaFuncAttributeMaxDynamicSharedMemorySize, SMEM_TOTAL);
    dim3 grid(SQ / BM, NHD, NB);   // (16,16,2) = 512 CTAs
    attn_hmma<<<grid, NT, SMEM_TOTAL>>>(Q, Bias, O);
}